// round 3
// baseline (speedup 1.0000x reference)
#include <cuda_runtime.h>

#define Bn 64
#define Sn 512
#define Hn 768
#define H4 192
#define Cn 50
#define Mn 2000
#define Tn 32768

#define MCAP 512
#define MWCAP 128
#define UCAP 1024
#define UWCAP 192
#define NCAP 128
#define LCAP 128

// ---------------- scratch (static device globals; no allocs) ----------------
__device__ __align__(16) float g_nts[Tn];
__device__ __align__(16) float g_mts[Tn];
__device__ __align__(16) float g_uts[Tn];
__device__ __align__(16) float g_names_emb[Cn * Bn * Hn];   // 9.8 MB
__device__ float g_nscore[Cn * Bn];
__device__ int   g_m_idx[Mn * MCAP];
__device__ float g_m_w[Mn * MCAP];
__device__ int   g_m_cnt[Mn];
__device__ __align__(16) float g_m_emb[Mn * Hn];            // 6.1 MB
__device__ float g_m_score[Mn];
__device__ int   g_u_idx[Cn * UCAP];
__device__ float g_u_w[Cn * UCAP];
__device__ int   g_u_cnt[Cn];
__device__ __align__(16) float g_u_part[Cn * 4 * Hn];

__device__ __forceinline__ float wsum(float v) {
    for (int o = 16; o; o >>= 1) v += __shfl_xor_sync(0xffffffffu, v, o);
    return v;
}
__device__ __forceinline__ float wmaxr(float v) {
    for (int o = 16; o; o >>= 1) v = fmaxf(v, __shfl_xor_sync(0xffffffffu, v, o));
    return v;
}

// ---------------- K1: per-token scores (3 fused dots, one story pass) -------
__global__ void __launch_bounds__(256) k_tok(const float* __restrict__ se,
                      const float* __restrict__ wn,
                      const float* __restrict__ wm,
                      const float* __restrict__ wu) {
    __shared__ float s_wn[Hn], s_wm[Hn], s_wu[Hn];
    for (int i = threadIdx.x; i < Hn; i += blockDim.x) {
        s_wn[i] = wn[i]; s_wm[i] = wm[i]; s_wu[i] = wu[i];
    }
    __syncthreads();
    int warp = threadIdx.x >> 5, lane = threadIdx.x & 31;
    int t = blockIdx.x * 8 + warp;
    const float4* row = (const float4*)(se + (size_t)t * Hn);
    const float4* w1 = (const float4*)s_wn;
    const float4* w2 = (const float4*)s_wm;
    const float4* w3 = (const float4*)s_wu;
    float a = 0.f, b = 0.f, c = 0.f;
#pragma unroll
    for (int k = 0; k < 6; k++) {
        int i = lane + 32 * k;
        float4 x = row[i];
        float4 p = w1[i]; a += x.x * p.x + x.y * p.y + x.z * p.z + x.w * p.w;
        float4 q = w2[i]; b += x.x * q.x + x.y * q.y + x.z * q.z + x.w * q.w;
        float4 r = w3[i]; c += x.x * r.x + x.y * r.y + x.z * r.z + x.w * r.w;
    }
    a = wsum(a); b = wsum(b); c = wsum(c);
    if (lane == 0) { g_nts[t] = a; g_mts[t] = b; g_uts[t] = c; }
}

// ---------------- K_scan: mask row -> compact (idx, softmax weight) ---------
template <bool UTT>
__global__ void __launch_bounds__(256) k_scan(const float* __restrict__ mask) {
    constexpr int CAP  = UTT ? UCAP : MCAP;
    constexpr int WCAP = UTT ? UWCAP : MWCAP;
    int r = blockIdx.x;
    __shared__ int   st_idx[8][WCAP];
    __shared__ float st_val[8][WCAP];
    __shared__ int wcnt[8];
    __shared__ int woff[8];
    __shared__ int s_n;
    __shared__ int   f_idx[CAP];
    __shared__ float f_val[CAP];
    __shared__ float s_red[8];
    int tid = threadIdx.x, warp = tid >> 5, lane = tid & 31;
    const float* tok = UTT ? g_uts : g_mts;
    const float4* m4 = (const float4*)(mask + (size_t)r * Tn);
    unsigned mlt = (1u << lane) - 1u;
    int cnt = 0;
    int base = warp * 1024;   // float4 units; warp covers 4096 tokens
    for (int it = 0; it < 32; it++) {
        int i4 = base + it * 32 + lane;
        float4 v = m4[i4];
        bool o0 = (v.x == 0.f), o1 = (v.y == 0.f), o2 = (v.z == 0.f), o3 = (v.w == 0.f);
        unsigned b0 = __ballot_sync(0xffffffffu, o0);
        unsigned b1 = __ballot_sync(0xffffffffu, o1);
        unsigned b2 = __ballot_sync(0xffffffffu, o2);
        unsigned b3 = __ballot_sync(0xffffffffu, o3);
        int before = cnt + __popc(b0 & mlt) + __popc(b1 & mlt) + __popc(b2 & mlt) + __popc(b3 & mlt);
        int t0 = i4 * 4, k = 0;
        if (o0) { int p = before + k; if (p < WCAP) { st_idx[warp][p] = t0;     st_val[warp][p] = tok[t0];     } k++; }
        if (o1) { int p = before + k; if (p < WCAP) { st_idx[warp][p] = t0 + 1; st_val[warp][p] = tok[t0 + 1]; } k++; }
        if (o2) { int p = before + k; if (p < WCAP) { st_idx[warp][p] = t0 + 2; st_val[warp][p] = tok[t0 + 2]; } k++; }
        if (o3) { int p = before + k; if (p < WCAP) { st_idx[warp][p] = t0 + 3; st_val[warp][p] = tok[t0 + 3]; } k++; }
        cnt += __popc(b0) + __popc(b1) + __popc(b2) + __popc(b3);
    }
    if (lane == 0) wcnt[warp] = min(cnt, WCAP);
    __syncthreads();
    if (tid == 0) {
        int s = 0;
        for (int w = 0; w < 8; w++) { woff[w] = s; s += wcnt[w]; }
        s_n = min(s, CAP);
    }
    __syncthreads();
    {
        int off = woff[warp], wc = wcnt[warp];
        for (int j = lane; j < wc; j += 32) {
            int p = off + j;
            if (p < CAP) { f_idx[p] = st_idx[warp][j]; f_val[p] = st_val[warp][j]; }
        }
    }
    __syncthreads();
    int n = s_n;
    if (n > 0) {
        float mx = -3.4e38f;
        for (int j = tid; j < n; j += 256) mx = fmaxf(mx, f_val[j]);
        mx = wmaxr(mx);
        if (lane == 0) s_red[warp] = mx;
        __syncthreads();
        if (tid == 0) { float v = -3.4e38f; for (int w = 0; w < 8; w++) v = fmaxf(v, s_red[w]); s_red[0] = v; }
        __syncthreads();
        mx = s_red[0];
        __syncthreads();
        float sm = 0.f;
        for (int j = tid; j < n; j += 256) sm += expf(f_val[j] - mx);
        sm = wsum(sm);
        if (lane == 0) s_red[warp] = sm;
        __syncthreads();
        if (tid == 0) { float v = 0.f; for (int w = 0; w < 8; w++) v += s_red[w]; s_red[0] = v; }
        __syncthreads();
        float inv = 1.0f / s_red[0];
        int* oi   = UTT ? g_u_idx : g_m_idx;
        float* ow = UTT ? g_u_w   : g_m_w;
        for (int j = tid; j < n; j += 256) {
            oi[r * CAP + j] = f_idx[j];
            ow[r * CAP + j] = expf(f_val[j] - mx) * inv;
        }
    }
    if (tid == 0) { if (UTT) g_u_cnt[r] = n; else g_m_cnt[r] = n; }
}

// ---------------- K_names: per (c,b) sparse attention pool ------------------
__global__ void __launch_bounds__(192) k_names(const float* __restrict__ se,
                        const float* __restrict__ nmask,
                        const float* __restrict__ w_name) {
    int c = blockIdx.x, b = blockIdx.y;
    int tid = threadIdx.x, warp = tid >> 5, lane = tid & 31;
    __shared__ int s_idx[NCAP];
    __shared__ float s_w[NCAP];
    __shared__ int s_cnt;
    __shared__ float s_red[8];
    if (warp == 0) {
        unsigned mlt = (1u << lane) - 1u;
        int cnt = 0;
        for (int base = 0; base < Sn; base += 32) {
            int s = base + lane;
            bool ok = (nmask[c * Sn + s] == 0.0f);
            unsigned bal = __ballot_sync(0xffffffffu, ok);
            if (ok) {
                int p = cnt + __popc(bal & mlt);
                if (p < NCAP) { s_idx[p] = s; s_w[p] = g_nts[b * Sn + s]; }
            }
            cnt += __popc(bal);
        }
        cnt = min(cnt, NCAP);
        if (lane == 0) s_cnt = cnt;
        __syncwarp();
        float mx = -3.4e38f;
        for (int j = lane; j < cnt; j += 32) mx = fmaxf(mx, s_w[j]);
        mx = wmaxr(mx);
        float sm = 0.f;
        for (int j = lane; j < cnt; j += 32) sm += expf(s_w[j] - mx);
        sm = wsum(sm);
        float inv = 1.0f / sm;
        for (int j = lane; j < cnt; j += 32) s_w[j] = expf(s_w[j] - mx) * inv;
    }
    __syncthreads();
    int n = s_cnt;
    const float4* se4 = (const float4*)se;
    size_t rb = (size_t)b * Sn * H4;
    float4 acc = make_float4(0.f, 0.f, 0.f, 0.f);
    int j = 0;
    for (; j + 2 <= n; j += 2) {
        float w0 = s_w[j], w1 = s_w[j + 1];
        float4 x0 = se4[rb + (size_t)s_idx[j] * H4 + tid];
        float4 x1 = se4[rb + (size_t)s_idx[j + 1] * H4 + tid];
        acc.x = fmaf(w0, x0.x, fmaf(w1, x1.x, acc.x));
        acc.y = fmaf(w0, x0.y, fmaf(w1, x1.y, acc.y));
        acc.z = fmaf(w0, x0.z, fmaf(w1, x1.z, acc.z));
        acc.w = fmaf(w0, x0.w, fmaf(w1, x1.w, acc.w));
    }
    if (j < n) {
        float w0 = s_w[j];
        float4 x0 = se4[rb + (size_t)s_idx[j] * H4 + tid];
        acc.x = fmaf(w0, x0.x, acc.x); acc.y = fmaf(w0, x0.y, acc.y);
        acc.z = fmaf(w0, x0.z, acc.z); acc.w = fmaf(w0, x0.w, acc.w);
    }
    ((float4*)g_names_emb)[((size_t)c * Bn + b) * H4 + tid] = acc;
    float4 ww = ((const float4*)w_name)[tid];
    float p = acc.x * ww.x + acc.y * ww.y + acc.z * ww.z + acc.w * ww.w;
    p = wsum(p);
    if (lane == 0) s_red[warp] = p;
    __syncthreads();
    if (tid == 0) {
        float s = 0.f;
        for (int w = 0; w < 6; w++) s += s_red[w];
        g_nscore[c * Bn + b] = s;
    }
}

// ---------------- K_memb: per-mention gather-sum + score --------------------
__global__ void __launch_bounds__(192) k_memb(const float* __restrict__ se, const float* __restrict__ w_men) {
    int m = blockIdx.x, tid = threadIdx.x, warp = tid >> 5, lane = tid & 31;
    __shared__ int s_idx[MCAP];
    __shared__ float s_w[MCAP];
    __shared__ float s_red[8];
    int n = g_m_cnt[m];
    for (int j = tid; j < n; j += 192) {
        s_idx[j] = g_m_idx[m * MCAP + j];
        s_w[j]   = g_m_w[m * MCAP + j];
    }
    __syncthreads();
    const float4* se4 = (const float4*)se;
    float4 acc = make_float4(0.f, 0.f, 0.f, 0.f);
    int j = 0;
    for (; j + 4 <= n; j += 4) {
        int t0 = s_idx[j], t1 = s_idx[j + 1], t2 = s_idx[j + 2], t3 = s_idx[j + 3];
        float w0 = s_w[j], w1 = s_w[j + 1], w2 = s_w[j + 2], w3 = s_w[j + 3];
        float4 x0 = se4[(size_t)t0 * H4 + tid];
        float4 x1 = se4[(size_t)t1 * H4 + tid];
        float4 x2 = se4[(size_t)t2 * H4 + tid];
        float4 x3 = se4[(size_t)t3 * H4 + tid];
        acc.x = fmaf(w0, x0.x, fmaf(w1, x1.x, fmaf(w2, x2.x, fmaf(w3, x3.x, acc.x))));
        acc.y = fmaf(w0, x0.y, fmaf(w1, x1.y, fmaf(w2, x2.y, fmaf(w3, x3.y, acc.y))));
        acc.z = fmaf(w0, x0.z, fmaf(w1, x1.z, fmaf(w2, x2.z, fmaf(w3, x3.z, acc.z))));
        acc.w = fmaf(w0, x0.w, fmaf(w1, x1.w, fmaf(w2, x2.w, fmaf(w3, x3.w, acc.w))));
    }
    for (; j < n; j++) {
        float w = s_w[j];
        float4 x = se4[(size_t)s_idx[j] * H4 + tid];
        acc.x = fmaf(w, x.x, acc.x); acc.y = fmaf(w, x.y, acc.y);
        acc.z = fmaf(w, x.z, acc.z); acc.w = fmaf(w, x.w, acc.w);
    }
    ((float4*)g_m_emb)[(size_t)m * H4 + tid] = acc;
    float4 ww = ((const float4*)w_men)[tid];
    float p = acc.x * ww.x + acc.y * ww.y + acc.z * ww.z + acc.w * ww.w;
    p = wsum(p);
    if (lane == 0) s_red[warp] = p;
    __syncthreads();
    if (tid == 0) {
        float s = 0.f;
        for (int w = 0; w < 6; w++) s += s_red[w];
        g_m_score[m] = s;
    }
}

// ---------------- K_upart: utterance gather, 4-way list split ---------------
__global__ void __launch_bounds__(192) k_upart(const float* __restrict__ se) {
    int c = blockIdx.x, q = blockIdx.y, tid = threadIdx.x;
    int n = g_u_cnt[c];
    const float4* se4 = (const float4*)se;
    float4 acc = make_float4(0.f, 0.f, 0.f, 0.f);
    for (int j = q; j < n; j += 4) {
        int t = g_u_idx[c * UCAP + j];
        float w = g_u_w[c * UCAP + j];
        float4 x = se4[(size_t)t * H4 + tid];
        acc.x = fmaf(w, x.x, acc.x); acc.y = fmaf(w, x.y, acc.y);
        acc.z = fmaf(w, x.z, acc.z); acc.w = fmaf(w, x.w, acc.w);
    }
    ((float4*)g_u_part)[((size_t)(c * 4 + q)) * H4 + tid] = acc;
}

// ---------------- K_final: per-char combine ---------------------------------
__global__ void __launch_bounds__(192) k_final(const int* __restrict__ seg,
                        const float* __restrict__ w_comb,
                        float* __restrict__ out) {
    int c = blockIdx.x, tid = threadIdx.x, warp = tid >> 5, lane = tid & 31;
    __shared__ float s_red[8];
    __shared__ float s_nw[Bn];
    __shared__ int s_list[LCAP];
    __shared__ float s_wgt[LCAP];
    __shared__ int s_n;
    __shared__ float s_a[3];
    __shared__ float s_parts[24];

    // name softmax over blocks
    float mx = -3.4e38f;
    for (int b = tid; b < Bn; b += 192) mx = fmaxf(mx, g_nscore[c * Bn + b]);
    mx = wmaxr(mx);
    if (lane == 0) s_red[warp] = mx;
    __syncthreads();
    if (tid == 0) { float v = -3.4e38f; for (int w = 0; w < 6; w++) v = fmaxf(v, s_red[w]); s_red[0] = v; }
    __syncthreads();
    mx = s_red[0];
    __syncthreads();
    float sm = 0.f;
    for (int b = tid; b < Bn; b += 192) sm += expf(g_nscore[c * Bn + b] - mx);
    sm = wsum(sm);
    if (lane == 0) s_red[warp] = sm;
    __syncthreads();
    if (tid == 0) { float v = 0.f; for (int w = 0; w < 6; w++) v += s_red[w]; s_red[0] = v; }
    __syncthreads();
    float inv = 1.0f / s_red[0];
    for (int b = tid; b < Bn; b += 192) s_nw[b] = expf(g_nscore[c * Bn + b] - mx) * inv;
    __syncthreads();

    // mention segment softmax (warp0 builds ordered list)
    // NOTE: Mn (2000) is NOT a multiple of 32 -> must guard the tail lanes.
    if (warp == 0) {
        unsigned mlt = (1u << lane) - 1u;
        int cnt = 0;
        for (int base = 0; base < Mn; base += 32) {
            int m = base + lane;
            bool ok = (m < Mn) && (seg[m] == c);
            unsigned bal = __ballot_sync(0xffffffffu, ok);
            if (ok) {
                int p = cnt + __popc(bal & mlt);
                if (p < LCAP) s_list[p] = m;
            }
            cnt += __popc(bal);
        }
        cnt = min(cnt, LCAP);
        if (lane == 0) s_n = cnt;
        __syncwarp();
        if (cnt > 0) {
            float m2 = -3.4e38f;
            for (int j = lane; j < cnt; j += 32) m2 = fmaxf(m2, g_m_score[s_list[j]]);
            m2 = wmaxr(m2);
            float sm2 = 0.f;
            for (int j = lane; j < cnt; j += 32) sm2 += expf(g_m_score[s_list[j]] - m2);
            sm2 = wsum(sm2);
            float inv2 = 1.0f / sm2;
            for (int j = lane; j < cnt; j += 32) s_wgt[j] = expf(g_m_score[s_list[j]] - m2) * inv2;
        }
    }
    __syncthreads();

    // accumulate three representations (per-thread float4 slice of H)
    const float4* ne4 = (const float4*)g_names_emb;
    float4 aN = make_float4(0.f, 0.f, 0.f, 0.f);
    for (int b = 0; b < Bn; b++) {
        float w = s_nw[b];
        float4 x = ne4[((size_t)c * Bn + b) * H4 + tid];
        aN.x = fmaf(w, x.x, aN.x); aN.y = fmaf(w, x.y, aN.y);
        aN.z = fmaf(w, x.z, aN.z); aN.w = fmaf(w, x.w, aN.w);
    }
    int nm = s_n;
    const float4* me4 = (const float4*)g_m_emb;
    float4 aM = make_float4(0.f, 0.f, 0.f, 0.f);
    for (int j = 0; j < nm; j++) {
        float w = s_wgt[j];
        float4 x = me4[(size_t)s_list[j] * H4 + tid];
        aM.x = fmaf(w, x.x, aM.x); aM.y = fmaf(w, x.y, aM.y);
        aM.z = fmaf(w, x.z, aM.z); aM.w = fmaf(w, x.w, aM.w);
    }
    const float4* up4 = (const float4*)g_u_part;
    float4 aU = make_float4(0.f, 0.f, 0.f, 0.f);
    for (int q = 0; q < 4; q++) {
        float4 x = up4[((size_t)(c * 4 + q)) * H4 + tid];
        aU.x += x.x; aU.y += x.y; aU.z += x.z; aU.w += x.w;
    }
    bool hasM = nm > 0;
    bool hasU = g_u_cnt[c] > 0;

    // 3 combine scores
    float4 wc4 = ((const float4*)w_comb)[tid];
    float p0 = aN.x * wc4.x + aN.y * wc4.y + aN.z * wc4.z + aN.w * wc4.w;
    float p1 = aM.x * wc4.x + aM.y * wc4.y + aM.z * wc4.z + aM.w * wc4.w;
    float p2 = aU.x * wc4.x + aU.y * wc4.y + aU.z * wc4.z + aU.w * wc4.w;
    p0 = wsum(p0); p1 = wsum(p1); p2 = wsum(p2);
    if (lane == 0) { s_parts[warp] = p0; s_parts[8 + warp] = p1; s_parts[16 + warp] = p2; }
    __syncthreads();
    if (tid == 0) {
        float s0 = 0.f, s1 = 0.f, s2 = 0.f;
        for (int w = 0; w < 6; w++) { s0 += s_parts[w]; s1 += s_parts[8 + w]; s2 += s_parts[16 + w]; }
        float m3 = s0;
        if (hasM) m3 = fmaxf(m3, s1);
        if (hasU) m3 = fmaxf(m3, s2);
        float e0 = expf(s0 - m3);
        float e1 = hasM ? expf(s1 - m3) : 0.0f;
        float e2 = hasU ? expf(s2 - m3) : 0.0f;
        float d = e0 + e1 + e2;
        s_a[0] = e0 / d; s_a[1] = e1 / d; s_a[2] = e2 / d;
    }
    __syncthreads();
    float a0 = s_a[0], a1 = s_a[1], a2 = s_a[2];
    float4 o;
    o.x = a0 * aN.x + a1 * aM.x + a2 * aU.x;
    o.y = a0 * aN.y + a1 * aM.y + a2 * aU.y;
    o.z = a0 * aN.z + a1 * aM.z + a2 * aU.z;
    o.w = a0 * aN.w + a1 * aM.w + a2 * aU.w;
    ((float4*)out)[(size_t)c * H4 + tid] = o;
}

// ---------------- launch -----------------------------------------------------
extern "C" void kernel_launch(void* const* d_in, const int* in_sizes, int n_in,
                              void* d_out, int out_size) {
    const float* se         = (const float*)d_in[0];
    const float* names_mask = (const float*)d_in[1];
    const float* utt_mask   = (const float*)d_in[2];
    const float* men_mask   = (const float*)d_in[3];
    const int*   seg        = (const int*)d_in[4];
    const float* w_name_tok = (const float*)d_in[5];
    const float* w_name     = (const float*)d_in[7];
    const float* w_men_tok  = (const float*)d_in[9];
    const float* w_men      = (const float*)d_in[11];
    const float* w_utt      = (const float*)d_in[13];
    const float* w_comb     = (const float*)d_in[15];
    float* out = (float*)d_out;

    k_tok<<<Tn / 8, 256>>>(se, w_name_tok, w_men_tok, w_utt);
    k_scan<false><<<Mn, 256>>>(men_mask);
    k_scan<true><<<Cn, 256>>>(utt_mask);
    k_names<<<dim3(Cn, Bn), 192>>>(se, names_mask, w_name);
    k_memb<<<Mn, 192>>>(se, w_men);
    k_upart<<<dim3(Cn, 4), 192>>>(se);
    k_final<<<Cn, 192>>>(seg, w_comb, out);
}

// round 6
// speedup vs baseline: 1.2061x; 1.2061x over previous
#include <cuda_runtime.h>
#include <cuda_fp16.h>

#define Bn 64
#define Sn 512
#define Hn 768
#define H4 192
#define Cn 50
#define Mn 2000
#define Tn 32768

#define MCAP 512
#define MWCAP 128
#define UCAP 1024
#define UWCAP 192
#define NCAP 128
#define LCAP 128
#define USPLIT 8

// ---------------- scratch (static device globals; no allocs) ----------------
__device__ __align__(16) float g_nts[Tn];
__device__ __align__(16) float g_mts[Tn];
__device__ __align__(16) float g_uts[Tn];
__device__ __align__(16) __half g_se_h[(size_t)Tn * Hn];    // 50 MB fp16 story copy
__device__ __align__(16) float g_names_emb[Cn * Bn * Hn];   // 9.8 MB
__device__ float g_nscore[Cn * Bn];
__device__ int   g_m_idx[Mn * MCAP];
__device__ float g_m_w[Mn * MCAP];
__device__ int   g_m_cnt[Mn];
__device__ __align__(16) float g_m_emb[Mn * Hn];            // 6.1 MB
__device__ float g_m_score[Mn];
__device__ int   g_u_idx[Cn * UCAP];
__device__ float g_u_w[Cn * UCAP];
__device__ int   g_u_cnt[Cn];
__device__ __align__(16) float g_u_part[Cn * USPLIT * Hn];

__device__ __forceinline__ float wsum(float v) {
    for (int o = 16; o; o >>= 1) v += __shfl_xor_sync(0xffffffffu, v, o);
    return v;
}
__device__ __forceinline__ float wmaxr(float v) {
    for (int o = 16; o; o >>= 1) v = fmaxf(v, __shfl_xor_sync(0xffffffffu, v, o));
    return v;
}

// unpack one uint2 (4 halves) and fma into a float4 accumulator
__device__ __forceinline__ void h4fma(float4& acc, float w, uint2 r) {
    __half2 h0 = *(__half2*)&r.x;
    __half2 h1 = *(__half2*)&r.y;
    float2 fa = __half22float2(h0);
    float2 fb = __half22float2(h1);
    acc.x = fmaf(w, fa.x, acc.x); acc.y = fmaf(w, fa.y, acc.y);
    acc.z = fmaf(w, fb.x, acc.z); acc.w = fmaf(w, fb.y, acc.w);
}

// ---------------- K1: per-token scores + fp16 story copy --------------------
__global__ void __launch_bounds__(256) k_tok(const float* __restrict__ se,
                      const float* __restrict__ wn,
                      const float* __restrict__ wm,
                      const float* __restrict__ wu) {
    __shared__ float s_wn[Hn], s_wm[Hn], s_wu[Hn];
    for (int i = threadIdx.x; i < Hn; i += blockDim.x) {
        s_wn[i] = wn[i]; s_wm[i] = wm[i]; s_wu[i] = wu[i];
    }
    __syncthreads();
    int warp = threadIdx.x >> 5, lane = threadIdx.x & 31;
    int t = blockIdx.x * 8 + warp;
    const float4* row = (const float4*)(se + (size_t)t * Hn);
    uint2* out_h = ((uint2*)g_se_h) + (size_t)t * H4;   // 192 uint2 per row (4 halves each)
    const float4* w1 = (const float4*)s_wn;
    const float4* w2 = (const float4*)s_wm;
    const float4* w3 = (const float4*)s_wu;
    float a = 0.f, b = 0.f, c = 0.f;
#pragma unroll
    for (int k = 0; k < 6; k++) {
        int i = lane + 32 * k;
        float4 x = row[i];
        float4 p = w1[i]; a += x.x * p.x + x.y * p.y + x.z * p.z + x.w * p.w;
        float4 q = w2[i]; b += x.x * q.x + x.y * q.y + x.z * q.z + x.w * q.w;
        float4 r = w3[i]; c += x.x * r.x + x.y * r.y + x.z * r.z + x.w * r.w;
        __half2 h0 = __float22half2_rn(make_float2(x.x, x.y));
        __half2 h1 = __float22half2_rn(make_float2(x.z, x.w));
        uint2 packed;
        packed.x = *(unsigned*)&h0;
        packed.y = *(unsigned*)&h1;
        out_h[i] = packed;
    }
    a = wsum(a); b = wsum(b); c = wsum(c);
    if (lane == 0) { g_nts[t] = a; g_mts[t] = b; g_uts[t] = c; }
}

// ---------------- K_scan: mask row -> compact (idx, softmax weight) ---------
template <bool UTT>
__global__ void __launch_bounds__(256) k_scan(const float* __restrict__ mask) {
    constexpr int CAP  = UTT ? UCAP : MCAP;
    constexpr int WCAP = UTT ? UWCAP : MWCAP;
    int r = blockIdx.x;
    __shared__ int   st_idx[8][WCAP];
    __shared__ float st_val[8][WCAP];
    __shared__ int wcnt[8];
    __shared__ int woff[8];
    __shared__ int s_n;
    __shared__ int   f_idx[CAP];
    __shared__ float f_val[CAP];
    __shared__ float s_red[8];
    int tid = threadIdx.x, warp = tid >> 5, lane = tid & 31;
    const float* tok = UTT ? g_uts : g_mts;
    const float4* m4 = (const float4*)(mask + (size_t)r * Tn);
    unsigned mlt = (1u << lane) - 1u;
    int cnt = 0;
    int base = warp * 1024;   // float4 units; warp covers 4096 tokens
    for (int it = 0; it < 32; it++) {
        int i4 = base + it * 32 + lane;
        float4 v = m4[i4];
        bool o0 = (v.x == 0.f), o1 = (v.y == 0.f), o2 = (v.z == 0.f), o3 = (v.w == 0.f);
        unsigned b0 = __ballot_sync(0xffffffffu, o0);
        unsigned b1 = __ballot_sync(0xffffffffu, o1);
        unsigned b2 = __ballot_sync(0xffffffffu, o2);
        unsigned b3 = __ballot_sync(0xffffffffu, o3);
        int before = cnt + __popc(b0 & mlt) + __popc(b1 & mlt) + __popc(b2 & mlt) + __popc(b3 & mlt);
        int t0 = i4 * 4, k = 0;
        if (o0) { int p = before + k; if (p < WCAP) { st_idx[warp][p] = t0;     st_val[warp][p] = tok[t0];     } k++; }
        if (o1) { int p = before + k; if (p < WCAP) { st_idx[warp][p] = t0 + 1; st_val[warp][p] = tok[t0 + 1]; } k++; }
        if (o2) { int p = before + k; if (p < WCAP) { st_idx[warp][p] = t0 + 2; st_val[warp][p] = tok[t0 + 2]; } k++; }
        if (o3) { int p = before + k; if (p < WCAP) { st_idx[warp][p] = t0 + 3; st_val[warp][p] = tok[t0 + 3]; } k++; }
        cnt += __popc(b0) + __popc(b1) + __popc(b2) + __popc(b3);
    }
    if (lane == 0) wcnt[warp] = min(cnt, WCAP);
    __syncthreads();
    if (tid == 0) {
        int s = 0;
        for (int w = 0; w < 8; w++) { woff[w] = s; s += wcnt[w]; }
        s_n = min(s, CAP);
    }
    __syncthreads();
    {
        int off = woff[warp], wc = wcnt[warp];
        for (int j = lane; j < wc; j += 32) {
            int p = off + j;
            if (p < CAP) { f_idx[p] = st_idx[warp][j]; f_val[p] = st_val[warp][j]; }
        }
    }
    __syncthreads();
    int n = s_n;
    if (n > 0) {
        float mx = -3.4e38f;
        for (int j = tid; j < n; j += 256) mx = fmaxf(mx, f_val[j]);
        mx = wmaxr(mx);
        if (lane == 0) s_red[warp] = mx;
        __syncthreads();
        if (tid == 0) { float v = -3.4e38f; for (int w = 0; w < 8; w++) v = fmaxf(v, s_red[w]); s_red[0] = v; }
        __syncthreads();
        mx = s_red[0];
        __syncthreads();
        float sm = 0.f;
        for (int j = tid; j < n; j += 256) sm += expf(f_val[j] - mx);
        sm = wsum(sm);
        if (lane == 0) s_red[warp] = sm;
        __syncthreads();
        if (tid == 0) { float v = 0.f; for (int w = 0; w < 8; w++) v += s_red[w]; s_red[0] = v; }
        __syncthreads();
        float inv = 1.0f / s_red[0];
        int* oi   = UTT ? g_u_idx : g_m_idx;
        float* ow = UTT ? g_u_w   : g_m_w;
        for (int j = tid; j < n; j += 256) {
            oi[r * CAP + j] = f_idx[j];
            ow[r * CAP + j] = expf(f_val[j] - mx) * inv;
        }
    }
    if (tid == 0) { if (UTT) g_u_cnt[r] = n; else g_m_cnt[r] = n; }
}

// ---------------- K_names: per (c,b) sparse attention pool (fp16 gather) ----
__global__ void __launch_bounds__(192) k_names(const float* __restrict__ nmask,
                        const float* __restrict__ w_name) {
    int c = blockIdx.x, b = blockIdx.y;
    int tid = threadIdx.x, warp = tid >> 5, lane = tid & 31;
    __shared__ int s_idx[NCAP];
    __shared__ float s_w[NCAP];
    __shared__ int s_cnt;
    __shared__ float s_red[8];
    if (warp == 0) {
        unsigned mlt = (1u << lane) - 1u;
        int cnt = 0;
        for (int base = 0; base < Sn; base += 32) {
            int s = base + lane;
            bool ok = (nmask[c * Sn + s] == 0.0f);
            unsigned bal = __ballot_sync(0xffffffffu, ok);
            if (ok) {
                int p = cnt + __popc(bal & mlt);
                if (p < NCAP) { s_idx[p] = s; s_w[p] = g_nts[b * Sn + s]; }
            }
            cnt += __popc(bal);
        }
        cnt = min(cnt, NCAP);
        if (lane == 0) s_cnt = cnt;
        __syncwarp();
        float mx = -3.4e38f;
        for (int j = lane; j < cnt; j += 32) mx = fmaxf(mx, s_w[j]);
        mx = wmaxr(mx);
        float sm = 0.f;
        for (int j = lane; j < cnt; j += 32) sm += expf(s_w[j] - mx);
        sm = wsum(sm);
        float inv = 1.0f / sm;
        for (int j = lane; j < cnt; j += 32) s_w[j] = expf(s_w[j] - mx) * inv;
    }
    __syncthreads();
    int n = s_cnt;
    const uint2* se2 = (const uint2*)g_se_h;
    size_t rb = (size_t)b * Sn * H4;
    float4 acc = make_float4(0.f, 0.f, 0.f, 0.f);
    int j = 0;
    for (; j + 4 <= n; j += 4) {
        float w0 = s_w[j], w1 = s_w[j + 1], w2 = s_w[j + 2], w3 = s_w[j + 3];
        uint2 r0 = se2[rb + (size_t)s_idx[j] * H4 + tid];
        uint2 r1 = se2[rb + (size_t)s_idx[j + 1] * H4 + tid];
        uint2 r2 = se2[rb + (size_t)s_idx[j + 2] * H4 + tid];
        uint2 r3 = se2[rb + (size_t)s_idx[j + 3] * H4 + tid];
        h4fma(acc, w0, r0); h4fma(acc, w1, r1); h4fma(acc, w2, r2); h4fma(acc, w3, r3);
    }
    for (; j < n; j++) {
        uint2 r0 = se2[rb + (size_t)s_idx[j] * H4 + tid];
        h4fma(acc, s_w[j], r0);
    }
    ((float4*)g_names_emb)[((size_t)c * Bn + b) * H4 + tid] = acc;
    float4 ww = ((const float4*)w_name)[tid];
    float p = acc.x * ww.x + acc.y * ww.y + acc.z * ww.z + acc.w * ww.w;
    p = wsum(p);
    if (lane == 0) s_red[warp] = p;
    __syncthreads();
    if (tid == 0) {
        float s = 0.f;
        for (int w = 0; w < 6; w++) s += s_red[w];
        g_nscore[c * Bn + b] = s;
    }
}

// ---------------- K_memb: per-mention gather-sum + score (fp16 gather) ------
__global__ void __launch_bounds__(192) k_memb(const float* __restrict__ w_men) {
    int m = blockIdx.x, tid = threadIdx.x, warp = tid >> 5, lane = tid & 31;
    __shared__ int s_idx[MCAP];
    __shared__ float s_w[MCAP];
    __shared__ float s_red[8];
    int n = g_m_cnt[m];
    for (int j = tid; j < n; j += 192) {
        s_idx[j] = g_m_idx[m * MCAP + j];
        s_w[j]   = g_m_w[m * MCAP + j];
    }
    __syncthreads();
    const uint2* se2 = (const uint2*)g_se_h;
    float4 acc = make_float4(0.f, 0.f, 0.f, 0.f);
    int j = 0;
    for (; j + 8 <= n; j += 8) {
        uint2 r0 = se2[(size_t)s_idx[j]     * H4 + tid];
        uint2 r1 = se2[(size_t)s_idx[j + 1] * H4 + tid];
        uint2 r2 = se2[(size_t)s_idx[j + 2] * H4 + tid];
        uint2 r3 = se2[(size_t)s_idx[j + 3] * H4 + tid];
        uint2 r4 = se2[(size_t)s_idx[j + 4] * H4 + tid];
        uint2 r5 = se2[(size_t)s_idx[j + 5] * H4 + tid];
        uint2 r6 = se2[(size_t)s_idx[j + 6] * H4 + tid];
        uint2 r7 = se2[(size_t)s_idx[j + 7] * H4 + tid];
        h4fma(acc, s_w[j],     r0); h4fma(acc, s_w[j + 1], r1);
        h4fma(acc, s_w[j + 2], r2); h4fma(acc, s_w[j + 3], r3);
        h4fma(acc, s_w[j + 4], r4); h4fma(acc, s_w[j + 5], r5);
        h4fma(acc, s_w[j + 6], r6); h4fma(acc, s_w[j + 7], r7);
    }
    for (; j < n; j++) {
        uint2 r0 = se2[(size_t)s_idx[j] * H4 + tid];
        h4fma(acc, s_w[j], r0);
    }
    ((float4*)g_m_emb)[(size_t)m * H4 + tid] = acc;
    float4 ww = ((const float4*)w_men)[tid];
    float p = acc.x * ww.x + acc.y * ww.y + acc.z * ww.z + acc.w * ww.w;
    p = wsum(p);
    if (lane == 0) s_red[warp] = p;
    __syncthreads();
    if (tid == 0) {
        float s = 0.f;
        for (int w = 0; w < 6; w++) s += s_red[w];
        g_m_score[m] = s;
    }
}

// ---------------- K_upart: utterance gather, USPLIT-way list split ----------
__global__ void __launch_bounds__(192) k_upart() {
    int c = blockIdx.x, q = blockIdx.y, tid = threadIdx.x;
    int n = g_u_cnt[c];
    const uint2* se2 = (const uint2*)g_se_h;
    float4 acc = make_float4(0.f, 0.f, 0.f, 0.f);
    int j = q;
    for (; j + 2 * USPLIT <= n + q; j += 2 * USPLIT) {
        int t0 = g_u_idx[c * UCAP + j];
        int t1 = g_u_idx[c * UCAP + j + USPLIT];
        float w0 = g_u_w[c * UCAP + j];
        float w1 = g_u_w[c * UCAP + j + USPLIT];
        uint2 r0 = se2[(size_t)t0 * H4 + tid];
        uint2 r1 = se2[(size_t)t1 * H4 + tid];
        h4fma(acc, w0, r0); h4fma(acc, w1, r1);
    }
    for (; j < n; j += USPLIT) {
        int t = g_u_idx[c * UCAP + j];
        float w = g_u_w[c * UCAP + j];
        uint2 r = se2[(size_t)t * H4 + tid];
        h4fma(acc, w, r);
    }
    ((float4*)g_u_part)[((size_t)(c * USPLIT + q)) * H4 + tid] = acc;
}

// ---------------- K_final: per-char combine ---------------------------------
__global__ void __launch_bounds__(192) k_final(const int* __restrict__ seg,
                        const float* __restrict__ w_comb,
                        float* __restrict__ out) {
    int c = blockIdx.x, tid = threadIdx.x, warp = tid >> 5, lane = tid & 31;
    __shared__ float s_red[8];
    __shared__ float s_nw[Bn];
    __shared__ int s_list[LCAP];
    __shared__ float s_wgt[LCAP];
    __shared__ int s_n;
    __shared__ float s_a[3];
    __shared__ float s_parts[24];

    // name softmax over blocks
    float mx = -3.4e38f;
    for (int b = tid; b < Bn; b += 192) mx = fmaxf(mx, g_nscore[c * Bn + b]);
    mx = wmaxr(mx);
    if (lane == 0) s_red[warp] = mx;
    __syncthreads();
    if (tid == 0) { float v = -3.4e38f; for (int w = 0; w < 6; w++) v = fmaxf(v, s_red[w]); s_red[0] = v; }
    __syncthreads();
    mx = s_red[0];
    __syncthreads();
    float sm = 0.f;
    for (int b = tid; b < Bn; b += 192) sm += expf(g_nscore[c * Bn + b] - mx);
    sm = wsum(sm);
    if (lane == 0) s_red[warp] = sm;
    __syncthreads();
    if (tid == 0) { float v = 0.f; for (int w = 0; w < 6; w++) v += s_red[w]; s_red[0] = v; }
    __syncthreads();
    float inv = 1.0f / s_red[0];
    for (int b = tid; b < Bn; b += 192) s_nw[b] = expf(g_nscore[c * Bn + b] - mx) * inv;
    __syncthreads();

    // mention segment softmax (warp0 builds ordered list)
    // NOTE: Mn (2000) is NOT a multiple of 32 -> guard tail lanes.
    if (warp == 0) {
        unsigned mlt = (1u << lane) - 1u;
        int cnt = 0;
        for (int base = 0; base < Mn; base += 32) {
            int m = base + lane;
            bool ok = (m < Mn) && (seg[m] == c);
            unsigned bal = __ballot_sync(0xffffffffu, ok);
            if (ok) {
                int p = cnt + __popc(bal & mlt);
                if (p < LCAP) s_list[p] = m;
            }
            cnt += __popc(bal);
        }
        cnt = min(cnt, LCAP);
        if (lane == 0) s_n = cnt;
        __syncwarp();
        if (cnt > 0) {
            float m2 = -3.4e38f;
            for (int j = lane; j < cnt; j += 32) m2 = fmaxf(m2, g_m_score[s_list[j]]);
            m2 = wmaxr(m2);
            float sm2 = 0.f;
            for (int j = lane; j < cnt; j += 32) sm2 += expf(g_m_score[s_list[j]] - m2);
            sm2 = wsum(sm2);
            float inv2 = 1.0f / sm2;
            for (int j = lane; j < cnt; j += 32) s_wgt[j] = expf(g_m_score[s_list[j]] - m2) * inv2;
        }
    }
    __syncthreads();

    // accumulate three representations (per-thread float4 slice of H)
    const float4* ne4 = (const float4*)g_names_emb;
    float4 aN = make_float4(0.f, 0.f, 0.f, 0.f);
    for (int b = 0; b < Bn; b++) {
        float w = s_nw[b];
        float4 x = ne4[((size_t)c * Bn + b) * H4 + tid];
        aN.x = fmaf(w, x.x, aN.x); aN.y = fmaf(w, x.y, aN.y);
        aN.z = fmaf(w, x.z, aN.z); aN.w = fmaf(w, x.w, aN.w);
    }
    int nm = s_n;
    const float4* me4 = (const float4*)g_m_emb;
    float4 aM = make_float4(0.f, 0.f, 0.f, 0.f);
    for (int j = 0; j < nm; j++) {
        float w = s_wgt[j];
        float4 x = me4[(size_t)s_list[j] * H4 + tid];
        aM.x = fmaf(w, x.x, aM.x); aM.y = fmaf(w, x.y, aM.y);
        aM.z = fmaf(w, x.z, aM.z); aM.w = fmaf(w, x.w, aM.w);
    }
    const float4* up4 = (const float4*)g_u_part;
    float4 aU = make_float4(0.f, 0.f, 0.f, 0.f);
    for (int q = 0; q < USPLIT; q++) {
        float4 x = up4[((size_t)(c * USPLIT + q)) * H4 + tid];
        aU.x += x.x; aU.y += x.y; aU.z += x.z; aU.w += x.w;
    }
    bool hasM = nm > 0;
    bool hasU = g_u_cnt[c] > 0;

    // 3 combine scores
    float4 wc4 = ((const float4*)w_comb)[tid];
    float p0 = aN.x * wc4.x + aN.y * wc4.y + aN.z * wc4.z + aN.w * wc4.w;
    float p1 = aM.x * wc4.x + aM.y * wc4.y + aM.z * wc4.z + aM.w * wc4.w;
    float p2 = aU.x * wc4.x + aU.y * wc4.y + aU.z * wc4.z + aU.w * wc4.w;
    p0 = wsum(p0); p1 = wsum(p1); p2 = wsum(p2);
    if (lane == 0) { s_parts[warp] = p0; s_parts[8 + warp] = p1; s_parts[16 + warp] = p2; }
    __syncthreads();
    if (tid == 0) {
        float s0 = 0.f, s1 = 0.f, s2 = 0.f;
        for (int w = 0; w < 6; w++) { s0 += s_parts[w]; s1 += s_parts[8 + w]; s2 += s_parts[16 + w]; }
        float m3 = s0;
        if (hasM) m3 = fmaxf(m3, s1);
        if (hasU) m3 = fmaxf(m3, s2);
        float e0 = expf(s0 - m3);
        float e1 = hasM ? expf(s1 - m3) : 0.0f;
        float e2 = hasU ? expf(s2 - m3) : 0.0f;
        float d = e0 + e1 + e2;
        s_a[0] = e0 / d; s_a[1] = e1 / d; s_a[2] = e2 / d;
    }
    __syncthreads();
    float a0 = s_a[0], a1 = s_a[1], a2 = s_a[2];
    float4 o;
    o.x = a0 * aN.x + a1 * aM.x + a2 * aU.x;
    o.y = a0 * aN.y + a1 * aM.y + a2 * aU.y;
    o.z = a0 * aN.z + a1 * aM.z + a2 * aU.z;
    o.w = a0 * aN.w + a1 * aM.w + a2 * aU.w;
    ((float4*)out)[(size_t)c * H4 + tid] = o;
}

// ---------------- launch -----------------------------------------------------
extern "C" void kernel_launch(void* const* d_in, const int* in_sizes, int n_in,
                              void* d_out, int out_size) {
    const float* se         = (const float*)d_in[0];
    const float* names_mask = (const float*)d_in[1];
    const float* utt_mask   = (const float*)d_in[2];
    const float* men_mask   = (const float*)d_in[3];
    const int*   seg        = (const int*)d_in[4];
    const float* w_name_tok = (const float*)d_in[5];
    const float* w_name     = (const float*)d_in[7];
    const float* w_men_tok  = (const float*)d_in[9];
    const float* w_men      = (const float*)d_in[11];
    const float* w_utt      = (const float*)d_in[13];
    const float* w_comb     = (const float*)d_in[15];
    float* out = (float*)d_out;

    k_tok<<<Tn / 8, 256>>>(se, w_name_tok, w_men_tok, w_utt);
    k_scan<false><<<Mn, 256>>>(men_mask);
    k_scan<true><<<Cn, 256>>>(utt_mask);
    k_names<<<dim3(Cn, Bn), 192>>>(names_mask, w_name);
    k_memb<<<Mn, 192>>>(w_men);
    k_upart<<<dim3(Cn, USPLIT), 192>>>();
    k_final<<<Cn, 192>>>(seg, w_comb, out);
}

// round 9
// speedup vs baseline: 1.2792x; 1.0606x over previous
#include <cuda_runtime.h>
#include <cuda_fp16.h>

#define Bn 64
#define Sn 512
#define Hn 768
#define H4 192
#define HU4 96
#define Cn 50
#define Mn 2000
#define Tn 32768

#define MCAP 512
#define MWCAP 128
#define UCAP 1024
#define UWCAP 192
#define NCAP 128
#define LCAP 128
#define USPLIT 8
#define GT 96

// ---------------- scratch (static device globals; no allocs) ----------------
__device__ __align__(16) float g_nts[Tn];
__device__ __align__(16) float g_mts[Tn];
__device__ __align__(16) float g_uts[Tn];
__device__ __align__(16) __half g_se_h[(size_t)Tn * Hn];    // 50 MB fp16 story copy
__device__ __align__(16) float g_names_emb[Cn * Bn * Hn];   // 9.8 MB
__device__ float g_nscore[Cn * Bn];
__device__ int   g_n_idx[Cn * NCAP];
__device__ int   g_n_cnt[Cn];
__device__ int   g_m_idx[Mn * MCAP];
__device__ float g_m_w[Mn * MCAP];
__device__ int   g_m_cnt[Mn];
__device__ __align__(16) float g_m_emb[Mn * Hn];            // 6.1 MB
__device__ float g_m_score[Mn];
__device__ int   g_u_idx[Cn * UCAP];
__device__ float g_u_w[Cn * UCAP];
__device__ int   g_u_cnt[Cn];
__device__ __align__(16) float g_u_part[Cn * USPLIT * Hn];

__device__ __forceinline__ float wsum(float v) {
    for (int o = 16; o; o >>= 1) v += __shfl_xor_sync(0xffffffffu, v, o);
    return v;
}
__device__ __forceinline__ float wmaxr(float v) {
    for (int o = 16; o; o >>= 1) v = fmaxf(v, __shfl_xor_sync(0xffffffffu, v, o));
    return v;
}

// unpack one uint4 (8 halves) and fma into 8-float accumulator
__device__ __forceinline__ void h8fma(float* acc, float w, uint4 r) {
    __half2 h0 = *(__half2*)&r.x;
    __half2 h1 = *(__half2*)&r.y;
    __half2 h2 = *(__half2*)&r.z;
    __half2 h3 = *(__half2*)&r.w;
    float2 f0 = __half22float2(h0), f1 = __half22float2(h1);
    float2 f2 = __half22float2(h2), f3 = __half22float2(h3);
    acc[0] = fmaf(w, f0.x, acc[0]); acc[1] = fmaf(w, f0.y, acc[1]);
    acc[2] = fmaf(w, f1.x, acc[2]); acc[3] = fmaf(w, f1.y, acc[3]);
    acc[4] = fmaf(w, f2.x, acc[4]); acc[5] = fmaf(w, f2.y, acc[5]);
    acc[6] = fmaf(w, f3.x, acc[6]); acc[7] = fmaf(w, f3.y, acc[7]);
}

// ---------------- K1: per-token scores + fp16 story copy --------------------
__global__ void __launch_bounds__(256) k_tok(const float* __restrict__ se,
                      const float* __restrict__ wn,
                      const float* __restrict__ wm,
                      const float* __restrict__ wu) {
    __shared__ float s_wn[Hn], s_wm[Hn], s_wu[Hn];
    for (int i = threadIdx.x; i < Hn; i += blockDim.x) {
        s_wn[i] = wn[i]; s_wm[i] = wm[i]; s_wu[i] = wu[i];
    }
    __syncthreads();
    int warp = threadIdx.x >> 5, lane = threadIdx.x & 31;
    int t = blockIdx.x * 8 + warp;
    const float4* row = (const float4*)(se + (size_t)t * Hn);
    uint2* out_h = ((uint2*)g_se_h) + (size_t)t * H4;
    const float4* w1 = (const float4*)s_wn;
    const float4* w2 = (const float4*)s_wm;
    const float4* w3 = (const float4*)s_wu;
    float a = 0.f, b = 0.f, c = 0.f;
#pragma unroll
    for (int k = 0; k < 6; k++) {
        int i = lane + 32 * k;
        float4 x = row[i];
        float4 p = w1[i]; a += x.x * p.x + x.y * p.y + x.z * p.z + x.w * p.w;
        float4 q = w2[i]; b += x.x * q.x + x.y * q.y + x.z * q.z + x.w * q.w;
        float4 r = w3[i]; c += x.x * r.x + x.y * r.y + x.z * r.z + x.w * r.w;
        __half2 h0 = __float22half2_rn(make_float2(x.x, x.y));
        __half2 h1 = __float22half2_rn(make_float2(x.z, x.w));
        uint2 packed;
        packed.x = *(unsigned*)&h0;
        packed.y = *(unsigned*)&h1;
        out_h[i] = packed;
    }
    a = wsum(a); b = wsum(b); c = wsum(c);
    if (lane == 0) { g_nts[t] = a; g_mts[t] = b; g_uts[t] = c; }
}

// ---------------- K_nscan: compact names mask once per character ------------
__global__ void __launch_bounds__(32) k_nscan(const float* __restrict__ nmask) {
    int c = blockIdx.x, lane = threadIdx.x;
    unsigned mlt = (1u << lane) - 1u;
    int cnt = 0;
    for (int base = 0; base < Sn; base += 32) {
        int s = base + lane;
        bool ok = (nmask[c * Sn + s] == 0.0f);
        unsigned bal = __ballot_sync(0xffffffffu, ok);
        if (ok) {
            int p = cnt + __popc(bal & mlt);
            if (p < NCAP) g_n_idx[c * NCAP + p] = s;
        }
        cnt += __popc(bal);
    }
    if (lane == 0) g_n_cnt[c] = min(cnt, NCAP);
}

// ---------------- K_scan: mask row -> compact (idx, softmax weight) ---------
template <bool UTT>
__global__ void __launch_bounds__(256) k_scan(const float* __restrict__ mask) {
    constexpr int CAP  = UTT ? UCAP : MCAP;
    constexpr int WCAP = UTT ? UWCAP : MWCAP;
    int r = blockIdx.x;
    __shared__ int   st_idx[8][WCAP];
    __shared__ float st_val[8][WCAP];
    __shared__ int wcnt[8];
    __shared__ int woff[8];
    __shared__ int s_n;
    __shared__ int   f_idx[CAP];
    __shared__ float f_val[CAP];
    __shared__ float s_red[8];
    int tid = threadIdx.x, warp = tid >> 5, lane = tid & 31;
    const float* tok = UTT ? g_uts : g_mts;
    const float4* m4 = (const float4*)(mask + (size_t)r * Tn);
    unsigned mlt = (1u << lane) - 1u;
    int cnt = 0;
    int base = warp * 1024;
    for (int it = 0; it < 32; it++) {
        int i4 = base + it * 32 + lane;
        float4 v = m4[i4];
        bool o0 = (v.x == 0.f), o1 = (v.y == 0.f), o2 = (v.z == 0.f), o3 = (v.w == 0.f);
        unsigned b0 = __ballot_sync(0xffffffffu, o0);
        unsigned b1 = __ballot_sync(0xffffffffu, o1);
        unsigned b2 = __ballot_sync(0xffffffffu, o2);
        unsigned b3 = __ballot_sync(0xffffffffu, o3);
        int before = cnt + __popc(b0 & mlt) + __popc(b1 & mlt) + __popc(b2 & mlt) + __popc(b3 & mlt);
        int t0 = i4 * 4, k = 0;
        if (o0) { int p = before + k; if (p < WCAP) { st_idx[warp][p] = t0;     st_val[warp][p] = tok[t0];     } k++; }
        if (o1) { int p = before + k; if (p < WCAP) { st_idx[warp][p] = t0 + 1; st_val[warp][p] = tok[t0 + 1]; } k++; }
        if (o2) { int p = before + k; if (p < WCAP) { st_idx[warp][p] = t0 + 2; st_val[warp][p] = tok[t0 + 2]; } k++; }
        if (o3) { int p = before + k; if (p < WCAP) { st_idx[warp][p] = t0 + 3; st_val[warp][p] = tok[t0 + 3]; } k++; }
        cnt += __popc(b0) + __popc(b1) + __popc(b2) + __popc(b3);
    }
    if (lane == 0) wcnt[warp] = min(cnt, WCAP);
    __syncthreads();
    if (tid == 0) {
        int s = 0;
        for (int w = 0; w < 8; w++) { woff[w] = s; s += wcnt[w]; }
        s_n = min(s, CAP);
    }
    __syncthreads();
    {
        int off = woff[warp], wc = wcnt[warp];
        for (int j = lane; j < wc; j += 32) {
            int p = off + j;
            if (p < CAP) { f_idx[p] = st_idx[warp][j]; f_val[p] = st_val[warp][j]; }
        }
    }
    __syncthreads();
    int n = s_n;
    if (n > 0) {
        float mx = -3.4e38f;
        for (int j = tid; j < n; j += 256) mx = fmaxf(mx, f_val[j]);
        mx = wmaxr(mx);
        if (lane == 0) s_red[warp] = mx;
        __syncthreads();
        if (tid == 0) { float v = -3.4e38f; for (int w = 0; w < 8; w++) v = fmaxf(v, s_red[w]); s_red[0] = v; }
        __syncthreads();
        mx = s_red[0];
        __syncthreads();
        float sm = 0.f;
        for (int j = tid; j < n; j += 256) sm += expf(f_val[j] - mx);
        sm = wsum(sm);
        if (lane == 0) s_red[warp] = sm;
        __syncthreads();
        if (tid == 0) { float v = 0.f; for (int w = 0; w < 8; w++) v += s_red[w]; s_red[0] = v; }
        __syncthreads();
        float inv = 1.0f / s_red[0];
        int* oi   = UTT ? g_u_idx : g_m_idx;
        float* ow = UTT ? g_u_w   : g_m_w;
        for (int j = tid; j < n; j += 256) {
            oi[r * CAP + j] = f_idx[j];
            ow[r * CAP + j] = expf(f_val[j] - mx) * inv;
        }
    }
    if (tid == 0) { if (UTT) g_u_cnt[r] = n; else g_m_cnt[r] = n; }
}

// ---------------- K_names: per (c,b) pool, precompacted list, uint4 gather --
__global__ void __launch_bounds__(192) k_names(const float* __restrict__ w_name) {
    int c = blockIdx.x, b = blockIdx.y;
    int tid = threadIdx.x, warp = tid >> 5, lane = tid & 31;
    __shared__ int s_idx[NCAP];
    __shared__ float s_w[NCAP];
    __shared__ int s_cnt;
    __shared__ float sb[GT * 8];
    __shared__ float s_red[4];
    if (warp == 0) {
        int cnt = g_n_cnt[c];
        if (lane == 0) s_cnt = cnt;
        for (int j = lane; j < cnt; j += 32) {
            int s = g_n_idx[c * NCAP + j];
            s_idx[j] = s;
            s_w[j] = g_nts[b * Sn + s];
        }
        __syncwarp();
        float mx = -3.4e38f;
        for (int j = lane; j < cnt; j += 32) mx = fmaxf(mx, s_w[j]);
        mx = wmaxr(mx);
        float sm = 0.f;
        for (int j = lane; j < cnt; j += 32) sm += expf(s_w[j] - mx);
        sm = wsum(sm);
        float inv = 1.0f / sm;
        for (int j = lane; j < cnt; j += 32) s_w[j] = expf(s_w[j] - mx) * inv;
    }
    __syncthreads();
    int n = s_cnt;
    int g = tid / GT, gt = tid - g * GT;
    int j0 = g ? (n / 2) : 0;
    int j1 = g ? n : (n / 2);
    const uint4* se = (const uint4*)g_se_h;   // row stride HU4 uint4
    size_t rb = (size_t)b * Sn * HU4;         // block offset (FIX: was missing)
    float acc[8];
#pragma unroll
    for (int k = 0; k < 8; k++) acc[k] = 0.f;
    int j = j0;
    for (; j + 4 <= j1; j += 4) {
        uint4 r0 = se[rb + (size_t)s_idx[j]     * HU4 + gt];
        uint4 r1 = se[rb + (size_t)s_idx[j + 1] * HU4 + gt];
        uint4 r2 = se[rb + (size_t)s_idx[j + 2] * HU4 + gt];
        uint4 r3 = se[rb + (size_t)s_idx[j + 3] * HU4 + gt];
        h8fma(acc, s_w[j], r0); h8fma(acc, s_w[j + 1], r1);
        h8fma(acc, s_w[j + 2], r2); h8fma(acc, s_w[j + 3], r3);
    }
    for (; j < j1; j++) {
        uint4 r = se[rb + (size_t)s_idx[j] * HU4 + gt];
        h8fma(acc, s_w[j], r);
    }
    if (g == 1) {
#pragma unroll
        for (int k = 0; k < 8; k++) sb[gt * 8 + k] = acc[k];
    }
    __syncthreads();
    if (g == 0) {
#pragma unroll
        for (int k = 0; k < 8; k++) acc[k] += sb[gt * 8 + k];
        float4 lo = make_float4(acc[0], acc[1], acc[2], acc[3]);
        float4 hi = make_float4(acc[4], acc[5], acc[6], acc[7]);
        float4* dst = ((float4*)g_names_emb) + ((size_t)(c * Bn + b)) * H4 + gt * 2;
        dst[0] = lo; dst[1] = hi;
        const float4* wn4 = (const float4*)w_name;
        float4 wl = wn4[gt * 2], wh = wn4[gt * 2 + 1];
        float p = acc[0] * wl.x + acc[1] * wl.y + acc[2] * wl.z + acc[3] * wl.w
                + acc[4] * wh.x + acc[5] * wh.y + acc[6] * wh.z + acc[7] * wh.w;
        p = wsum(p);
        if (lane == 0) s_red[warp] = p;
    }
    __syncthreads();
    if (tid == 0) g_nscore[c * Bn + b] = s_red[0] + s_red[1] + s_red[2];
}

// ---------------- K_memb: per-mention gather-sum + score (uint4) ------------
__global__ void __launch_bounds__(192) k_memb(const float* __restrict__ w_men) {
    int m = blockIdx.x, tid = threadIdx.x, warp = tid >> 5, lane = tid & 31;
    __shared__ int s_idx[MCAP];
    __shared__ float s_w[MCAP];
    __shared__ float sb[GT * 8];
    __shared__ float s_red[4];
    int n = g_m_cnt[m];
    for (int j = tid; j < n; j += 192) {
        s_idx[j] = g_m_idx[m * MCAP + j];
        s_w[j]   = g_m_w[m * MCAP + j];
    }
    __syncthreads();
    int g = tid / GT, gt = tid - g * GT;
    int j0 = g ? (n / 2) : 0;
    int j1 = g ? n : (n / 2);
    const uint4* se = (const uint4*)g_se_h;
    float acc[8];
#pragma unroll
    for (int k = 0; k < 8; k++) acc[k] = 0.f;
    int j = j0;
    for (; j + 4 <= j1; j += 4) {
        uint4 r0 = se[(size_t)s_idx[j]     * HU4 + gt];
        uint4 r1 = se[(size_t)s_idx[j + 1] * HU4 + gt];
        uint4 r2 = se[(size_t)s_idx[j + 2] * HU4 + gt];
        uint4 r3 = se[(size_t)s_idx[j + 3] * HU4 + gt];
        h8fma(acc, s_w[j], r0); h8fma(acc, s_w[j + 1], r1);
        h8fma(acc, s_w[j + 2], r2); h8fma(acc, s_w[j + 3], r3);
    }
    for (; j < j1; j++) {
        uint4 r = se[(size_t)s_idx[j] * HU4 + gt];
        h8fma(acc, s_w[j], r);
    }
    if (g == 1) {
#pragma unroll
        for (int k = 0; k < 8; k++) sb[gt * 8 + k] = acc[k];
    }
    __syncthreads();
    if (g == 0) {
#pragma unroll
        for (int k = 0; k < 8; k++) acc[k] += sb[gt * 8 + k];
        float4 lo = make_float4(acc[0], acc[1], acc[2], acc[3]);
        float4 hi = make_float4(acc[4], acc[5], acc[6], acc[7]);
        float4* dst = ((float4*)g_m_emb) + (size_t)m * H4 + gt * 2;
        dst[0] = lo; dst[1] = hi;
        const float4* wm4 = (const float4*)w_men;
        float4 wl = wm4[gt * 2], wh = wm4[gt * 2 + 1];
        float p = acc[0] * wl.x + acc[1] * wl.y + acc[2] * wl.z + acc[3] * wl.w
                + acc[4] * wh.x + acc[5] * wh.y + acc[6] * wh.z + acc[7] * wh.w;
        p = wsum(p);
        if (lane == 0) s_red[warp] = p;
    }
    __syncthreads();
    if (tid == 0) g_m_score[m] = s_red[0] + s_red[1] + s_red[2];
}

// ---------------- K_upart: utterance gather, USPLIT x 2-group split ---------
__global__ void __launch_bounds__(192) k_upart() {
    int c = blockIdx.x, q = blockIdx.y, tid = threadIdx.x;
    int n = g_u_cnt[c];
    int g = tid / GT, gt = tid - g * GT;
    int K = (n - q + USPLIT - 1) / USPLIT;   // entries for this q (n>=0, q<USPLIT)
    if (K < 0) K = 0;
    int k0 = g ? (K / 2) : 0;
    int k1 = g ? K : (K / 2);
    const uint4* se = (const uint4*)g_se_h;
    float acc[8];
#pragma unroll
    for (int k = 0; k < 8; k++) acc[k] = 0.f;
    int k = k0;
    for (; k + 2 <= k1; k += 2) {
        int ja = q + k * USPLIT, jb = q + (k + 1) * USPLIT;
        int ta = g_u_idx[c * UCAP + ja];
        int tb = g_u_idx[c * UCAP + jb];
        float wa = g_u_w[c * UCAP + ja];
        float wb = g_u_w[c * UCAP + jb];
        uint4 ra = se[(size_t)ta * HU4 + gt];
        uint4 rb = se[(size_t)tb * HU4 + gt];
        h8fma(acc, wa, ra); h8fma(acc, wb, rb);
    }
    for (; k < k1; k++) {
        int j = q + k * USPLIT;
        int t = g_u_idx[c * UCAP + j];
        float w = g_u_w[c * UCAP + j];
        uint4 r = se[(size_t)t * HU4 + gt];
        h8fma(acc, w, r);
    }
    __shared__ float sb[GT * 8];
    if (g == 1) {
#pragma unroll
        for (int kk = 0; kk < 8; kk++) sb[gt * 8 + kk] = acc[kk];
    }
    __syncthreads();
    if (g == 0) {
#pragma unroll
        for (int kk = 0; kk < 8; kk++) acc[kk] += sb[gt * 8 + kk];
        float4 lo = make_float4(acc[0], acc[1], acc[2], acc[3]);
        float4 hi = make_float4(acc[4], acc[5], acc[6], acc[7]);
        float4* dst = ((float4*)g_u_part) + ((size_t)(c * USPLIT + q)) * H4 + gt * 2;
        dst[0] = lo; dst[1] = hi;
    }
}

// ---------------- K_final: per-char combine ---------------------------------
__global__ void __launch_bounds__(192) k_final(const int* __restrict__ seg,
                        const float* __restrict__ w_comb,
                        float* __restrict__ out) {
    int c = blockIdx.x, tid = threadIdx.x, warp = tid >> 5, lane = tid & 31;
    __shared__ float s_red[8];
    __shared__ float s_nw[Bn];
    __shared__ int s_list[LCAP];
    __shared__ float s_wgt[LCAP];
    __shared__ int s_n;
    __shared__ float s_a[3];
    __shared__ float s_parts[24];

    // name softmax over blocks
    float mx = -3.4e38f;
    for (int b = tid; b < Bn; b += 192) mx = fmaxf(mx, g_nscore[c * Bn + b]);
    mx = wmaxr(mx);
    if (lane == 0) s_red[warp] = mx;
    __syncthreads();
    if (tid == 0) { float v = -3.4e38f; for (int w = 0; w < 6; w++) v = fmaxf(v, s_red[w]); s_red[0] = v; }
    __syncthreads();
    mx = s_red[0];
    __syncthreads();
    float sm = 0.f;
    for (int b = tid; b < Bn; b += 192) sm += expf(g_nscore[c * Bn + b] - mx);
    sm = wsum(sm);
    if (lane == 0) s_red[warp] = sm;
    __syncthreads();
    if (tid == 0) { float v = 0.f; for (int w = 0; w < 6; w++) v += s_red[w]; s_red[0] = v; }
    __syncthreads();
    float inv = 1.0f / s_red[0];
    for (int b = tid; b < Bn; b += 192) s_nw[b] = expf(g_nscore[c * Bn + b] - mx) * inv;
    __syncthreads();

    // mention segment softmax (warp0 builds ordered list)
    // NOTE: Mn (2000) is NOT a multiple of 32 -> guard tail lanes.
    if (warp == 0) {
        unsigned mlt = (1u << lane) - 1u;
        int cnt = 0;
        for (int base = 0; base < Mn; base += 32) {
            int m = base + lane;
            bool ok = (m < Mn) && (seg[m] == c);
            unsigned bal = __ballot_sync(0xffffffffu, ok);
            if (ok) {
                int p = cnt + __popc(bal & mlt);
                if (p < LCAP) s_list[p] = m;
            }
            cnt += __popc(bal);
        }
        cnt = min(cnt, LCAP);
        if (lane == 0) s_n = cnt;
        __syncwarp();
        if (cnt > 0) {
            float m2 = -3.4e38f;
            for (int j = lane; j < cnt; j += 32) m2 = fmaxf(m2, g_m_score[s_list[j]]);
            m2 = wmaxr(m2);
            float sm2 = 0.f;
            for (int j = lane; j < cnt; j += 32) sm2 += expf(g_m_score[s_list[j]] - m2);
            sm2 = wsum(sm2);
            float inv2 = 1.0f / sm2;
            for (int j = lane; j < cnt; j += 32) s_wgt[j] = expf(g_m_score[s_list[j]] - m2) * inv2;
        }
    }
    __syncthreads();

    // accumulate three representations (per-thread float4 slice of H)
    const float4* ne4 = (const float4*)g_names_emb;
    float4 aN = make_float4(0.f, 0.f, 0.f, 0.f);
    for (int b = 0; b < Bn; b++) {
        float w = s_nw[b];
        float4 x = ne4[((size_t)c * Bn + b) * H4 + tid];
        aN.x = fmaf(w, x.x, aN.x); aN.y = fmaf(w, x.y, aN.y);
        aN.z = fmaf(w, x.z, aN.z); aN.w = fmaf(w, x.w, aN.w);
    }
    int nm = s_n;
    const float4* me4 = (const float4*)g_m_emb;
    float4 aM = make_float4(0.f, 0.f, 0.f, 0.f);
    for (int j = 0; j < nm; j++) {
        float w = s_wgt[j];
        float4 x = me4[(size_t)s_list[j] * H4 + tid];
        aM.x = fmaf(w, x.x, aM.x); aM.y = fmaf(w, x.y, aM.y);
        aM.z = fmaf(w, x.z, aM.z); aM.w = fmaf(w, x.w, aM.w);
    }
    const float4* up4 = (const float4*)g_u_part;
    float4 aU = make_float4(0.f, 0.f, 0.f, 0.f);
    for (int q = 0; q < USPLIT; q++) {
        float4 x = up4[((size_t)(c * USPLIT + q)) * H4 + tid];
        aU.x += x.x; aU.y += x.y; aU.z += x.z; aU.w += x.w;
    }
    bool hasM = nm > 0;
    bool hasU = g_u_cnt[c] > 0;

    // 3 combine scores
    float4 wc4 = ((const float4*)w_comb)[tid];
    float p0 = aN.x * wc4.x + aN.y * wc4.y + aN.z * wc4.z + aN.w * wc4.w;
    float p1 = aM.x * wc4.x + aM.y * wc4.y + aM.z * wc4.z + aM.w * wc4.w;
    float p2 = aU.x * wc4.x + aU.y * wc4.y + aU.z * wc4.z + aU.w * wc4.w;
    p0 = wsum(p0); p1 = wsum(p1); p2 = wsum(p2);
    if (lane == 0) { s_parts[warp] = p0; s_parts[8 + warp] = p1; s_parts[16 + warp] = p2; }
    __syncthreads();
    if (tid == 0) {
        float s0 = 0.f, s1 = 0.f, s2 = 0.f;
        for (int w = 0; w < 6; w++) { s0 += s_parts[w]; s1 += s_parts[8 + w]; s2 += s_parts[16 + w]; }
        float m3 = s0;
        if (hasM) m3 = fmaxf(m3, s1);
        if (hasU) m3 = fmaxf(m3, s2);
        float e0 = expf(s0 - m3);
        float e1 = hasM ? expf(s1 - m3) : 0.0f;
        float e2 = hasU ? expf(s2 - m3) : 0.0f;
        float d = e0 + e1 + e2;
        s_a[0] = e0 / d; s_a[1] = e1 / d; s_a[2] = e2 / d;
    }
    __syncthreads();
    float a0 = s_a[0], a1 = s_a[1], a2 = s_a[2];
    float4 o;
    o.x = a0 * aN.x + a1 * aM.x + a2 * aU.x;
    o.y = a0 * aN.y + a1 * aM.y + a2 * aU.y;
    o.z = a0 * aN.z + a1 * aM.z + a2 * aU.z;
    o.w = a0 * aN.w + a1 * aM.w + a2 * aU.w;
    ((float4*)out)[(size_t)c * H4 + tid] = o;
}

// ---------------- launch -----------------------------------------------------
extern "C" void kernel_launch(void* const* d_in, const int* in_sizes, int n_in,
                              void* d_out, int out_size) {
    const float* se         = (const float*)d_in[0];
    const float* names_mask = (const float*)d_in[1];
    const float* utt_mask   = (const float*)d_in[2];
    const float* men_mask   = (const float*)d_in[3];
    const int*   seg        = (const int*)d_in[4];
    const float* w_name_tok = (const float*)d_in[5];
    const float* w_name     = (const float*)d_in[7];
    const float* w_men_tok  = (const float*)d_in[9];
    const float* w_men      = (const float*)d_in[11];
    const float* w_utt      = (const float*)d_in[13];
    const float* w_comb     = (const float*)d_in[15];
    float* out = (float*)d_out;

    k_tok<<<Tn / 8, 256>>>(se, w_name_tok, w_men_tok, w_utt);
    k_nscan<<<Cn, 32>>>(names_mask);
    k_names<<<dim3(Cn, Bn), 192>>>(w_name);          // se_h still L2-hot
    k_scan<true><<<Cn, 256>>>(utt_mask);
    k_upart<<<dim3(Cn, USPLIT), 192>>>();
    k_scan<false><<<Mn, 256>>>(men_mask);            // 262 MB stream
    k_memb<<<Mn, 192>>>(w_men);
    k_final<<<Cn, 192>>>(seg, w_comb, out);
}